// round 4
// baseline (speedup 1.0000x reference)
#include <cuda_runtime.h>
#include <cuda_bf16.h>

#define D 64
#define NUM_REL 32
#define THREADS 128
#define WARPS_PER_BLOCK (THREADS / 32)
#define SLICES 32
#define LIST_MAX 4096   // = full slice size -> compaction can never overflow

// ---------------------------------------------------------------------------
// f32x2 packed-math helpers (sm_103a FFMA2 — PTX-only)
// ---------------------------------------------------------------------------
__device__ __forceinline__ unsigned long long pack2(float x) {
    unsigned long long r;
    asm("mov.b64 %0, {%1, %1};" : "=l"(r) : "r"(__float_as_uint(x)));
    return r;
}
__device__ __forceinline__ unsigned long long fma2(unsigned long long a,
                                                   unsigned long long b,
                                                   unsigned long long c) {
    unsigned long long d;
    asm("fma.rn.f32x2 %0, %1, %2, %3;" : "=l"(d) : "l"(a), "l"(b), "l"(c));
    return d;
}
__device__ __forceinline__ float hsum2(unsigned long long v) {
    unsigned int lo, hi;
    asm("mov.b64 {%0, %1}, %2;" : "=r"(lo), "=r"(hi) : "l"(v));
    return __uint_as_float(lo) + __uint_as_float(hi);
}

// one R row (64 floats = 16 ulonglong2):
// tmp[2j]   += (a,a) * R[row][4j..4j+1]
// tmp[2j+1] += (a,a) * R[row][4j+2..4j+3]
__device__ __forceinline__ void row_fma(unsigned long long* __restrict__ tmp,
                                        const ulonglong2* __restrict__ rrow,
                                        float a) {
    unsigned long long a2 = pack2(a);
    #pragma unroll
    for (int j = 0; j < 16; j++) {
        ulonglong2 q = rrow[j];
        tmp[2 * j]     = fma2(a2, q.x, tmp[2 * j]);
        tmp[2 * j + 1] = fma2(a2, q.y, tmp[2 * j + 1]);
    }
}

#define ROW_STRIDE_U2 16   // 64 floats per row = 16 ulonglong2

// ---------------------------------------------------------------------------
// Single fused kernel.
// block = (relation r, slice s). Loads R[r] into smem, scans its slice of
// rels[] compacting matching sample ids into smem, then computes scores with
// packed f32x2 FMAs. All 32 lanes of a warp share the same R row per step,
// so every LDS.128 of R is a conflict-free broadcast.
// ---------------------------------------------------------------------------
__global__ void __launch_bounds__(THREADS, 3)
fused_kernel(const float* __restrict__ e1g,
             const float* __restrict__ e2g,
             const int*   __restrict__ rels,
             const float* __restrict__ relw,
             float* __restrict__ out,
             int B)
{
    __shared__ float sR[D * D];      // 16 KB
    __shared__ int   s_list[LIST_MAX];
    __shared__ int   s_cnt;

    const int r     = blockIdx.x;
    const int slice = blockIdx.y;

    if (threadIdx.x == 0) s_cnt = 0;

    // cooperative load of this relation's matrix (4096 floats)
    {
        const float4* src = reinterpret_cast<const float4*>(relw + r * (D * D));
        float4* dst = reinterpret_cast<float4*>(sR);
        #pragma unroll
        for (int i = threadIdx.x; i < (D * D) / 4; i += THREADS) dst[i] = src[i];
    }
    __syncthreads();   // covers s_cnt init + sR

    // scan this slice of rels[], compact matching sample ids
    {
        const int per = (B + SLICES - 1) / SLICES;      // 4096 for B=131072
        const int lo  = slice * per;
        const int hi  = (lo + per < B) ? (lo + per) : B;
        const int4* rv = reinterpret_cast<const int4*>(rels);
        for (int q = lo / 4 + threadIdx.x; q * 4 < hi; q += THREADS) {
            int4 v = rv[q];
            int base = q * 4;
            if (base + 0 < hi && v.x == r) s_list[atomicAdd(&s_cnt, 1)] = base + 0;
            if (base + 1 < hi && v.y == r) s_list[atomicAdd(&s_cnt, 1)] = base + 1;
            if (base + 2 < hi && v.z == r) s_list[atomicAdd(&s_cnt, 1)] = base + 2;
            if (base + 3 < hi && v.w == r) s_list[atomicAdd(&s_cnt, 1)] = base + 3;
        }
    }
    __syncthreads();

    const int count  = s_cnt;
    const int ntiles = (count + 31) >> 5;
    const int lane   = threadIdx.x & 31;
    const int warp   = threadIdx.x >> 5;

    for (int tile = warp; tile < ntiles; tile += WARPS_PER_BLOCK) {
        const int s      = (tile << 5) + lane;
        const bool valid = (s < count);
        const int b      = valid ? s_list[s] : s_list[0];

        const float4* p1 = reinterpret_cast<const float4*>(e1g) + b * (D / 4);

        // 32 packed accumulators = 64 e-columns
        unsigned long long tmp[32];
        #pragma unroll
        for (int j = 0; j < 32; j++) tmp[j] = 0ull;

        float4 a_next = p1[0];
        #pragma unroll 1
        for (int g = 0; g < 16; g++) {          // 4 d-rows per iteration
            float4 a = a_next;
            if (g < 15) a_next = p1[g + 1];     // one-ahead prefetch
            const ulonglong2* rrow =
                reinterpret_cast<const ulonglong2*>(sR + (g * 4) * D);
            row_fma(tmp, rrow + 0 * ROW_STRIDE_U2, a.x);
            row_fma(tmp, rrow + 1 * ROW_STRIDE_U2, a.y);
            row_fma(tmp, rrow + 2 * ROW_STRIDE_U2, a.z);
            row_fma(tmp, rrow + 3 * ROW_STRIDE_U2, a.w);
        }

        // final dot with e2 (packed), 2 accumulator chains
        const ulonglong2* p2 =
            reinterpret_cast<const ulonglong2*>(e2g + b * D);
        unsigned long long acc0 = 0ull, acc1 = 0ull;
        #pragma unroll
        for (int j = 0; j < 16; j++) {
            ulonglong2 u = p2[j];
            acc0 = fma2(tmp[2 * j],     u.x, acc0);
            acc1 = fma2(tmp[2 * j + 1], u.y, acc1);
        }
        float score = hsum2(acc0) + hsum2(acc1);

        if (valid) out[b] = score;
    }
}

// ---------------------------------------------------------------------------
// kernel_launch
// inputs (metadata order): embeds1 [B*64] f32, embeds2 [B*64] f32,
//                          rels [B] i32, rel_embeds [32*4096] f32
// output: [B] f32
// ---------------------------------------------------------------------------
extern "C" void kernel_launch(void* const* d_in, const int* in_sizes, int n_in,
                              void* d_out, int out_size) {
    const float* e1   = (const float*)d_in[0];
    const float* e2   = (const float*)d_in[1];
    const int*   rels = (const int*)d_in[2];
    const float* relw = (const float*)d_in[3];
    float* out = (float*)d_out;

    const int B = in_sizes[2];

    dim3 grid(NUM_REL, SLICES);
    fused_kernel<<<grid, THREADS>>>(e1, e2, rels, relw, out, B);
}

// round 5
// speedup vs baseline: 1.3122x; 1.3122x over previous
#include <cuda_runtime.h>

#define D 64
#define NUM_REL 32
#define MAXB 131072
#define GROUP 128
#define MAX_GROUPS (MAXB / GROUP + NUM_REL)   // 1056; sum ceil(n_r/128) <= this always
#define THREADS 128

// Scratch (static device globals — zero-initialized at module load)
__device__ int g_counts[NUM_REL];
__device__ int g_n[NUM_REL];
__device__ int g_table[MAX_GROUPS];
__device__ int g_idx[NUM_REL * MAXB];

// ---------------------------------------------------------------------------
// f32x2 packed-math helpers (sm_103a FFMA2 — PTX-only)
// ---------------------------------------------------------------------------
__device__ __forceinline__ unsigned long long pack2(float x) {
    unsigned long long r;
    asm("mov.b64 %0, {%1, %1};" : "=l"(r) : "r"(__float_as_uint(x)));
    return r;
}
__device__ __forceinline__ unsigned long long fma2(unsigned long long a,
                                                   unsigned long long b,
                                                   unsigned long long c) {
    unsigned long long d;
    asm("fma.rn.f32x2 %0, %1, %2, %3;" : "=l"(d) : "l"(a), "l"(b), "l"(c));
    return d;
}
__device__ __forceinline__ float hsum2(unsigned long long v) {
    unsigned int lo, hi;
    asm("mov.b64 {%0, %1}, %2;" : "=r"(lo), "=r"(hi) : "l"(v));
    return __uint_as_float(lo) + __uint_as_float(hi);
}

// ---------------------------------------------------------------------------
// Kernel 1: bucket sample ids by relation (g_counts zeroed by plan_kernel of
// the previous replay; zero-initialized at load for the very first call).
// ---------------------------------------------------------------------------
__global__ void bucket_kernel(const int* __restrict__ rels, int B) {
    __shared__ int s_count[NUM_REL];
    __shared__ int s_base[NUM_REL];
    int t = threadIdx.x;
    if (t < NUM_REL) s_count[t] = 0;
    __syncthreads();

    int i = blockIdx.x * blockDim.x + t;
    int r = 0, lp = 0;
    bool valid = (i < B);
    if (valid) {
        r  = rels[i];
        lp = atomicAdd(&s_count[r], 1);
    }
    __syncthreads();
    if (t < NUM_REL) s_base[t] = atomicAdd(&g_counts[t], s_count[t]);
    __syncthreads();
    if (valid) g_idx[r * MAXB + s_base[r] + lp] = i;
}

// ---------------------------------------------------------------------------
// Kernel 2: plan — build exact (rel, group) work table, snapshot counts,
// zero g_counts for the next graph replay. One warp.
// ---------------------------------------------------------------------------
__global__ void plan_kernel() {
    int t = threadIdx.x;           // t == relation id, 32 threads
    int n = g_counts[t];
    g_n[t] = n;
    g_counts[t] = 0;
    int ng = (n + GROUP - 1) / GROUP;

    // inclusive warp scan of ng
    int s = ng;
    #pragma unroll
    for (int o = 1; o < 32; o <<= 1) {
        int v = __shfl_up_sync(0xffffffffu, s, o);
        if (t >= o) s += v;
    }
    int start = s - ng;
    int total = __shfl_sync(0xffffffffu, s, 31);

    for (int g = 0; g < ng; g++) g_table[start + g] = t | (g << 8);
    for (int i = total + t; i < MAX_GROUPS; i += 32) g_table[i] = -1;
}

// ---------------------------------------------------------------------------
// Kernel 3: score. One block = one 128-sample group of one relation.
// Register-tiled GEMM: 128 threads as (mg 0..15) x (ng 0..7); each thread
// computes an 8x8 tile of T = E1_tile @ R with packed f32x2 FMAs, then the
// fused rowsum(T * E2) epilogue with a deterministic smem reduction.
// ---------------------------------------------------------------------------
__global__ void __launch_bounds__(THREADS, 4)
score_kernel(const float* __restrict__ e1g,
             const float* __restrict__ e2g,
             const float* __restrict__ relw,
             float* __restrict__ out)
{
    __shared__ float sR[D * D];          // 16 KB, R[k][n] row-major
    __shared__ float E1t[D * GROUP];     // 32 KB, E1t[k][m] (transposed tile)

    const int item = g_table[blockIdx.x];
    if (item < 0) return;
    const int r    = item & 255;
    const int grp  = item >> 8;
    const int cnt0 = g_n[r] - grp * GROUP;
    const int cnt  = cnt0 < GROUP ? cnt0 : GROUP;
    const int* __restrict__ idx = g_idx + r * MAXB + grp * GROUP;

    const int t = threadIdx.x;

    // load R[r] into smem
    {
        const float4* src = reinterpret_cast<const float4*>(relw + r * (D * D));
        float4* dst = reinterpret_cast<float4*>(sR);
        #pragma unroll
        for (int i = t; i < (D * D) / 4; i += THREADS) dst[i] = src[i];
    }

    // stage E1 rows transposed: E1t[k][m]
    const int bm = (t < cnt) ? idx[t] : -1;
    if (bm >= 0) {
        const float4* p1 = reinterpret_cast<const float4*>(e1g + bm * D);
        #pragma unroll
        for (int k4 = 0; k4 < 16; k4++) {
            float4 v = p1[k4];
            E1t[(k4 * 4 + 0) * GROUP + t] = v.x;
            E1t[(k4 * 4 + 1) * GROUP + t] = v.y;
            E1t[(k4 * 4 + 2) * GROUP + t] = v.z;
            E1t[(k4 * 4 + 3) * GROUP + t] = v.w;
        }
    }
    __syncthreads();

    const int mg = t & 15;   // m-group: samples mg*8 .. mg*8+7
    const int ng = t >> 4;   // n-group: cols   ng*8 .. ng*8+7
    const int m0 = mg * 8;
    const int n0 = ng * 8;

    // acc[i][j] = (T[m0+i][n0+2j], T[m0+i][n0+2j+1])
    unsigned long long acc[8][4];
    #pragma unroll
    for (int i = 0; i < 8; i++)
        #pragma unroll
        for (int j = 0; j < 4; j++) acc[i][j] = 0ull;

    const float* __restrict__ arow = E1t + m0;
    const float* __restrict__ brow = sR + n0;

    #pragma unroll 4
    for (int k = 0; k < D; k++) {
        float4 av0 = *reinterpret_cast<const float4*>(arow + k * GROUP);
        float4 av1 = *reinterpret_cast<const float4*>(arow + k * GROUP + 4);
        ulonglong2 bq0 = *reinterpret_cast<const ulonglong2*>(brow + k * D);
        ulonglong2 bq1 = *reinterpret_cast<const ulonglong2*>(brow + k * D + 4);

        unsigned long long a2[8];
        a2[0] = pack2(av0.x); a2[1] = pack2(av0.y);
        a2[2] = pack2(av0.z); a2[3] = pack2(av0.w);
        a2[4] = pack2(av1.x); a2[5] = pack2(av1.y);
        a2[6] = pack2(av1.z); a2[7] = pack2(av1.w);

        #pragma unroll
        for (int i = 0; i < 8; i++) {
            acc[i][0] = fma2(a2[i], bq0.x, acc[i][0]);
            acc[i][1] = fma2(a2[i], bq0.y, acc[i][1]);
            acc[i][2] = fma2(a2[i], bq1.x, acc[i][2]);
            acc[i][3] = fma2(a2[i], bq1.y, acc[i][3]);
        }
    }
    __syncthreads();   // everyone done reading E1t — safe to reuse as partials

    // epilogue: partial_i = sum over this thread's 8 cols of T[m_i][.] * e2[m_i][.]
    float* s_part = E1t;   // reuse: [8 ng][128 m]
    #pragma unroll
    for (int i = 0; i < 8; i++) {
        const int m = m0 + i;
        if (m < cnt) {
            const int b = idx[m];
            const ulonglong2* u =
                reinterpret_cast<const ulonglong2*>(e2g + b * D + n0);
            ulonglong2 u0 = u[0];
            ulonglong2 u1 = u[1];
            unsigned long long p = 0ull;
            p = fma2(acc[i][0], u0.x, p);
            p = fma2(acc[i][1], u0.y, p);
            p = fma2(acc[i][2], u1.x, p);
            p = fma2(acc[i][3], u1.y, p);
            s_part[ng * GROUP + m] = hsum2(p);
        }
    }
    __syncthreads();

    // deterministic fixed-order reduction + store
    if (t < cnt) {
        float s = 0.0f;
        #pragma unroll
        for (int j = 0; j < 8; j++) s += s_part[j * GROUP + t];
        out[bm] = s;
    }
}

// ---------------------------------------------------------------------------
// kernel_launch
// inputs (metadata order): embeds1 [B*64] f32, embeds2 [B*64] f32,
//                          rels [B] i32, rel_embeds [32*4096] f32
// output: [B] f32
// ---------------------------------------------------------------------------
extern "C" void kernel_launch(void* const* d_in, const int* in_sizes, int n_in,
                              void* d_out, int out_size) {
    const float* e1   = (const float*)d_in[0];
    const float* e2   = (const float*)d_in[1];
    const int*   rels = (const int*)d_in[2];
    const float* relw = (const float*)d_in[3];
    float* out = (float*)d_out;

    const int B = in_sizes[2];

    bucket_kernel<<<(B + 255) / 256, 256>>>(rels, B);
    plan_kernel<<<1, 32>>>();
    score_kernel<<<MAX_GROUPS, THREADS>>>(e1, e2, relw, out);
}

// round 6
// speedup vs baseline: 1.4892x; 1.1349x over previous
#include <cuda_runtime.h>

#define D 64
#define NUM_REL 32
#define MAXB 131072
#define GROUP 128
#define MAX_GROUPS (MAXB / GROUP + NUM_REL)   // 1056
#define THREADS 128

// Scratch (static device globals — zero-initialized at module load)
__device__ int g_counts[NUM_REL];
__device__ int g_n[NUM_REL];
__device__ int g_table[MAX_GROUPS];
__device__ int g_idx[NUM_REL * MAXB];
__device__ int g_done;

// ---------------------------------------------------------------------------
// f32x2 packed-math helpers (sm_103a FFMA2 — PTX-only)
// ---------------------------------------------------------------------------
__device__ __forceinline__ unsigned long long pack2(float x) {
    unsigned long long r;
    asm("mov.b64 %0, {%1, %1};" : "=l"(r) : "r"(__float_as_uint(x)));
    return r;
}
__device__ __forceinline__ unsigned long long fma2(unsigned long long a,
                                                   unsigned long long b,
                                                   unsigned long long c) {
    unsigned long long d;
    asm("fma.rn.f32x2 %0, %1, %2, %3;" : "=l"(d) : "l"(a), "l"(b), "l"(c));
    return d;
}
__device__ __forceinline__ float hsum2(unsigned long long v) {
    unsigned int lo, hi;
    asm("mov.b64 {%0, %1}, %2;" : "=r"(lo), "=r"(hi) : "l"(v));
    return __uint_as_float(lo) + __uint_as_float(hi);
}

// ---------------------------------------------------------------------------
// Kernel 1: bucket + (fused) plan.
// Warp-aggregated smem counting, global scatter, then the LAST block to
// finish builds the exact (rel, group) work table and re-zeroes counters
// for the next graph replay.
// ---------------------------------------------------------------------------
__global__ void bucket_kernel(const int* __restrict__ rels, int B) {
    __shared__ int s_count[NUM_REL];
    __shared__ int s_base[NUM_REL];
    __shared__ int s_last;
    const int t    = threadIdx.x;
    const int lane = t & 31;
    if (t < NUM_REL) s_count[t] = 0;
    __syncthreads();

    const int i = blockIdx.x * blockDim.x + t;
    int r = 0, lp = 0;
    const bool valid = (i < B);
    if (valid) r = rels[i];

    // warp-aggregated smem atomic
    {
        unsigned am = __ballot_sync(0xffffffffu, valid);
        if (valid) {
            unsigned mask   = __match_any_sync(am, r);
            int      leader = __ffs(mask) - 1;
            int      rank   = __popc(mask & ((1u << lane) - 1));
            int      base   = 0;
            if (lane == leader) base = atomicAdd(&s_count[r], __popc(mask));
            base = __shfl_sync(am, base, leader);
            lp = base + rank;
        }
    }
    __syncthreads();
    if (t < NUM_REL) s_base[t] = atomicAdd(&g_counts[t], s_count[t]);
    __syncthreads();
    if (valid) g_idx[r * MAXB + s_base[r] + lp] = i;

    // last-block-done: fused plan
    __threadfence();
    __syncthreads();
    if (t == 0) {
        int ticket = atomicAdd(&g_done, 1);
        s_last = (ticket == (int)gridDim.x - 1);
    }
    __syncthreads();
    if (s_last && t < 32) {
        int n = atomicAdd(&g_counts[t], 0);   // coherent read
        g_n[t] = n;
        g_counts[t] = 0;
        int ng = (n + GROUP - 1) / GROUP;

        // inclusive warp scan of ng
        int s = ng;
        #pragma unroll
        for (int o = 1; o < 32; o <<= 1) {
            int v = __shfl_up_sync(0xffffffffu, s, o);
            if (t >= o) s += v;
        }
        int start = s - ng;
        int total = __shfl_sync(0xffffffffu, s, 31);

        for (int g = 0; g < ng; g++) g_table[start + g] = t | (g << 8);
        for (int j = total + t; j < MAX_GROUPS; j += 32) g_table[j] = -1;
        if (t == 0) g_done = 0;
    }
}

// ---------------------------------------------------------------------------
// Kernel 2: score. One block = one 128-sample group of one relation.
// 128 threads as (mg 0..15) x (ng 0..7). Thread's m-tile is INTERLEAVED
// ({mg*4..+3} and {64+mg*4..+3}) so each 8-lane LDS.128 phase reads 8
// consecutive float4s -> conflict-free. b (R-row) loads are quarter-warp
// broadcasts. Packed f32x2 FMAs throughout.
// ---------------------------------------------------------------------------
__global__ void __launch_bounds__(THREADS, 4)
score_kernel(const float* __restrict__ e1g,
             const float* __restrict__ e2g,
             const float* __restrict__ relw,
             float* __restrict__ out)
{
    __shared__ float sR[D * D];          // 16 KB, R[k][n]
    __shared__ float E1t[D * GROUP];     // 32 KB, E1t[k][m]

    const int item = g_table[blockIdx.x];
    if (item < 0) return;
    const int r    = item & 255;
    const int grp  = item >> 8;
    const int cnt0 = g_n[r] - grp * GROUP;
    const int cnt  = cnt0 < GROUP ? cnt0 : GROUP;
    const int* __restrict__ idx = g_idx + r * MAXB + grp * GROUP;

    const int t = threadIdx.x;

    // load R[r] into smem
    {
        const float4* src = reinterpret_cast<const float4*>(relw + r * (D * D));
        float4* dst = reinterpret_cast<float4*>(sR);
        #pragma unroll
        for (int i = t; i < (D * D) / 4; i += THREADS) dst[i] = src[i];
    }

    // stage E1 rows transposed: E1t[k][m]
    const int bm = (t < cnt) ? idx[t] : -1;
    if (bm >= 0) {
        const float4* p1 = reinterpret_cast<const float4*>(e1g + bm * D);
        #pragma unroll
        for (int k4 = 0; k4 < 16; k4++) {
            float4 v = p1[k4];
            E1t[(k4 * 4 + 0) * GROUP + t] = v.x;
            E1t[(k4 * 4 + 1) * GROUP + t] = v.y;
            E1t[(k4 * 4 + 2) * GROUP + t] = v.z;
            E1t[(k4 * 4 + 3) * GROUP + t] = v.w;
        }
    }
    __syncthreads();

    const int mg = t & 15;   // m-groups: [mg*4, mg*4+4) and [64+mg*4, 64+mg*4+4)
    const int ng = t >> 4;   // n-group:  cols ng*8 .. ng*8+7
    const int m0 = mg * 4;
    const int n0 = ng * 8;

    // acc[i][j]: i 0-3 -> m = m0+i ; i 4-7 -> m = 64+m0+(i-4)
    //            j -> cols (n0+2j, n0+2j+1)
    unsigned long long acc[8][4];
    #pragma unroll
    for (int i = 0; i < 8; i++)
        #pragma unroll
        for (int j = 0; j < 4; j++) acc[i][j] = 0ull;

    const float* __restrict__ arow = E1t + m0;
    const float* __restrict__ brow = sR + n0;

    #pragma unroll 4
    for (int k = 0; k < D; k++) {
        float4 av0 = *reinterpret_cast<const float4*>(arow + k * GROUP);
        float4 av1 = *reinterpret_cast<const float4*>(arow + k * GROUP + 64);
        ulonglong2 bq0 = *reinterpret_cast<const ulonglong2*>(brow + k * D);
        ulonglong2 bq1 = *reinterpret_cast<const ulonglong2*>(brow + k * D + 4);

        unsigned long long a2[8];
        a2[0] = pack2(av0.x); a2[1] = pack2(av0.y);
        a2[2] = pack2(av0.z); a2[3] = pack2(av0.w);
        a2[4] = pack2(av1.x); a2[5] = pack2(av1.y);
        a2[6] = pack2(av1.z); a2[7] = pack2(av1.w);

        #pragma unroll
        for (int i = 0; i < 8; i++) {
            acc[i][0] = fma2(a2[i], bq0.x, acc[i][0]);
            acc[i][1] = fma2(a2[i], bq0.y, acc[i][1]);
            acc[i][2] = fma2(a2[i], bq1.x, acc[i][2]);
            acc[i][3] = fma2(a2[i], bq1.y, acc[i][3]);
        }
    }
    __syncthreads();   // done reading E1t — reuse as partials

    // epilogue: partial = sum over this thread's 8 cols of T[m][.] * e2[m][.]
    float* s_part = E1t;   // [8 ng][128 m]
    #pragma unroll
    for (int i = 0; i < 8; i++) {
        const int m = (i < 4) ? (m0 + i) : (64 + m0 + (i - 4));
        if (m < cnt) {
            const int b = idx[m];
            const ulonglong2* u =
                reinterpret_cast<const ulonglong2*>(e2g + b * D + n0);
            ulonglong2 u0 = u[0];
            ulonglong2 u1 = u[1];
            unsigned long long p = 0ull;
            p = fma2(acc[i][0], u0.x, p);
            p = fma2(acc[i][1], u0.y, p);
            p = fma2(acc[i][2], u1.x, p);
            p = fma2(acc[i][3], u1.y, p);
            s_part[ng * GROUP + m] = hsum2(p);
        }
    }
    __syncthreads();

    // deterministic fixed-order reduction + store
    if (t < cnt) {
        float s = 0.0f;
        #pragma unroll
        for (int j = 0; j < 8; j++) s += s_part[j * GROUP + t];
        out[bm] = s;
    }
}

// ---------------------------------------------------------------------------
// kernel_launch
// inputs (metadata order): embeds1 [B*64] f32, embeds2 [B*64] f32,
//                          rels [B] i32, rel_embeds [32*4096] f32
// output: [B] f32
// ---------------------------------------------------------------------------
extern "C" void kernel_launch(void* const* d_in, const int* in_sizes, int n_in,
                              void* d_out, int out_size) {
    const float* e1   = (const float*)d_in[0];
    const float* e2   = (const float*)d_in[1];
    const int*   rels = (const int*)d_in[2];
    const float* relw = (const float*)d_in[3];
    float* out = (float*)d_out;

    const int B = in_sizes[2];

    bucket_kernel<<<(B + 255) / 256, 256>>>(rels, B);
    score_kernel<<<MAX_GROUPS, THREADS>>>(e1, e2, relw, out);
}